// round 15
// baseline (speedup 1.0000x reference)
#include <cuda_runtime.h>
#include <cuda_bf16.h>
#include <math_constants.h>

#define BB 4
#define KK 8192
#define THREADS 256
#define RM 4                     // rows per thread (ty 0..7 -> 32 rows/block)
#define CN 4                     // cols per thread per pass (tx 0..31 -> 128)
#define ROWS_B 32
#define COLS_P 128
#define COLHALF 4096
#define NPASS (COLHALF / COLS_P) // 32
#define RBLOCKS 64
#define RTHREADS 256

// Per-point min of u = 0.5*|p-t|^2, COMPLEMENT-encoded: e = ~bits(u), u>=0.
// min(u) == max(e); e>0 always, so zero-initialized globals are the "+inf"
// sentinel (no init kernel). reduce_kernel resets slots to 0 for graph replay.
__device__ unsigned int g_enc[2][BB * KK];   // [0]=per-pred rows, [1]=per-target cols
__device__ float g_part[3][RBLOCKS];

// One pass over the pair matrix serves BOTH chamfer directions (268M pairs
// instead of 536M):  u_ij = h_i + w_ij,  w_ij = tw_j - p_i.t_j.
// Per pair: 3 FFMA + 1 FADD (fma pipe) + 2 FMNMX (alu pipe, non-binding).
// Pass loop unrolled x2 so shared-buffer indices are compile-time constants
// (R11's fused attempt drowned in dynamic-index address arithmetic).
__global__ void __launch_bounds__(THREADS, 5)
chamfer_kernel(const float* __restrict__ pred, const float* __restrict__ target) {
    const int b       = blockIdx.z;
    const int rowblk  = blockIdx.x;
    const int colbase = blockIdx.y * COLHALF;
    const int tid = threadIdx.x;
    const int tx = tid & 31, ty = tid >> 5;

    __shared__ float4 tile[2][COLS_P];        // x,y,z, 0.5*t^2
    __shared__ float  scol[2][8][COLS_P];     // per-ty col-min partials

    float nx[RM], ny[RM], nz[RM], h[RM], m[RM];
    const int row0 = rowblk * ROWS_B + ty * RM;
    const float* pr = pred + ((size_t)b * KK + row0) * 3;
#pragma unroll
    for (int r = 0; r < RM; r++) {
        float x = pr[r * 3], y = pr[r * 3 + 1], z = pr[r * 3 + 2];
        nx[r] = -x; ny[r] = -y; nz[r] = -z;
        h[r] = 0.5f * (x * x + y * y + z * z);
        m[r] = CUDART_INF_F;
    }

    const float* tg = target + ((size_t)b * KK + colbase) * 3;
    if (tid < COLS_P) {
        float x = tg[tid * 3], y = tg[tid * 3 + 1], z = tg[tid * 3 + 2];
        tile[0][tid] = make_float4(x, y, z, 0.5f * (x * x + y * y + z * z));
    }
    __syncthreads();

#pragma unroll 2
    for (int pass = 0; pass < NPASS; pass++) {
        const int buf = pass & 1;             // compile-time after x2 unroll
        if (pass + 1 < NPASS && tid < COLS_P) {
            const float* t2 = tg + ((pass + 1) * COLS_P + tid) * 3;
            float x = t2[0], y = t2[1], z = t2[2];
            tile[buf ^ 1][tid] = make_float4(x, y, z, 0.5f * (x * x + y * y + z * z));
        }

        float4 cp[CN];
        float cpart[CN];
#pragma unroll
        for (int c = 0; c < CN; c++) {
            cp[c] = tile[buf][tx + 32 * c];
            cpart[c] = CUDART_INF_F;
        }

#pragma unroll
        for (int c = 0; c < CN; c++) {
#pragma unroll
            for (int r = 0; r < RM; r++) {
                float w = fmaf(nz[r], cp[c].z, cp[c].w);
                w = fmaf(ny[r], cp[c].y, w);
                w = fmaf(nx[r], cp[c].x, w);
                m[r] = fminf(m[r], w);
                cpart[c] = fminf(cpart[c], w + h[r]);
            }
        }

#pragma unroll
        for (int c = 0; c < CN; c++) scol[buf][ty][tx + 32 * c] = cpart[c];
        __syncthreads();

        // Flush this pass's 128 cols (each col touched once per block).
        if (tid < COLS_P) {
            float v = scol[buf][0][tid];
#pragma unroll
            for (int t = 1; t < 8; t++) v = fminf(v, scol[buf][t][tid]);
            atomicMax(&g_enc[1][(size_t)b * KK + colbase + pass * COLS_P + tid],
                      ~__float_as_uint(fmaxf(v, 0.0f)));
        }
    }

    // Row finalize: one shuffle tree per row at kernel end.
#pragma unroll
    for (int r = 0; r < RM; r++) {
        float w = m[r];
#pragma unroll
        for (int off = 16; off > 0; off >>= 1)
            w = fminf(w, __shfl_xor_sync(0xFFFFFFFFu, w, off));
        if (tx == 0) {
            float u = fmaxf(w + h[r], 0.0f);
            atomicMax(&g_enc[0][(size_t)b * KK + row0 + r], ~__float_as_uint(u));
        }
    }
}

// Multi-block reduce (latency-parallel) + slot reset for graph replay. d=sqrt(2u).
__global__ void __launch_bounds__(RTHREADS)
reduce_kernel(const float* __restrict__ mask) {
    float s0 = 0.f, s1 = 0.f, s2 = 0.f;
    for (int i = blockIdx.x * RTHREADS + threadIdx.x; i < BB * KK;
         i += RBLOCKS * RTHREADS) {
        float mk = mask[i];
        float u0 = __uint_as_float(~g_enc[0][i]);
        float u1 = __uint_as_float(~g_enc[1][i]);
        g_enc[0][i] = 0u;
        g_enc[1][i] = 0u;
        s0 = fmaf(sqrtf(2.0f * u0), mk, s0);
        s1 = fmaf(sqrtf(2.0f * u1), mk, s1);
        s2 += mk;
    }
    __shared__ float sh[3][RTHREADS];
    const int tid = threadIdx.x;
    sh[0][tid] = s0; sh[1][tid] = s1; sh[2][tid] = s2;
    __syncthreads();
    for (int off = RTHREADS / 2; off > 0; off >>= 1) {
        if (tid < off) {
            sh[0][tid] += sh[0][tid + off];
            sh[1][tid] += sh[1][tid + off];
            sh[2][tid] += sh[2][tid + off];
        }
        __syncthreads();
    }
    if (tid == 0) {
        g_part[0][blockIdx.x] = sh[0][0];
        g_part[1][blockIdx.x] = sh[1][0];
        g_part[2][blockIdx.x] = sh[2][0];
    }
}

__global__ void __launch_bounds__(64)
final_kernel(float* __restrict__ out) {
    const int t = threadIdx.x;               // 64 threads = 2 warps
    float a = g_part[0][t], b = g_part[1][t], c = g_part[2][t];
#pragma unroll
    for (int off = 16; off > 0; off >>= 1) {
        a += __shfl_down_sync(0xFFFFFFFFu, a, off);
        b += __shfl_down_sync(0xFFFFFFFFu, b, off);
        c += __shfl_down_sync(0xFFFFFFFFu, c, off);
    }
    __shared__ float sh[3][2];
    if ((t & 31) == 0) { sh[0][t >> 5] = a; sh[1][t >> 5] = b; sh[2][t >> 5] = c; }
    __syncthreads();
    if (t == 0) {
        float s0 = sh[0][0] + sh[0][1];
        float s1 = sh[1][0] + sh[1][1];
        float s2 = sh[2][0] + sh[2][1];
        out[0] = (s0 + s1) / (2.0f * (s2 + 1e-8f));
    }
}

extern "C" void kernel_launch(void* const* d_in, const int* in_sizes, int n_in,
                              void* d_out, int out_size) {
    const float* pred   = (const float*)d_in[0];
    const float* target = (const float*)d_in[1];
    const float* mask   = (const float*)d_in[2];
    float* out = (float*)d_out;

    dim3 grid(KK / ROWS_B, KK / COLHALF, BB);   // 256 x 2 x 4 = 2048 blocks
    chamfer_kernel<<<grid, THREADS>>>(pred, target);

    reduce_kernel<<<RBLOCKS, RTHREADS>>>(mask);
    final_kernel<<<1, 64>>>(out);
}

// round 16
// speedup vs baseline: 1.1527x; 1.1527x over previous
#include <cuda_runtime.h>
#include <cuda_bf16.h>
#include <math_constants.h>

#define BB 4
#define KK 8192
#define THREADS 256
#define RM 4
#define NSPLIT 32
#define TN 256                // targets per block tile
#define TNP (TN / 2)          // 128 packed pairs
#define RBLOCKS 64
#define RTHREADS 256

// Per-point min distance, COMPLEMENT-encoded: e = ~bits(d), d >= 0.
// min(d) == max(e); e > 0 always, so zero-initialized globals are the "+inf"
// sentinel (no init kernel). reduce_kernel resets slots to 0 for graph replay.
__device__ unsigned int g_enc[2][BB * KK];
__device__ float g_part[3][RBLOCKS];
__device__ unsigned int g_done;   // zero-init; reset by last block each run

typedef unsigned long long u64;

__device__ __forceinline__ u64 pack2(float lo, float hi) {
    u64 r; asm("mov.b64 %0, {%1, %2};" : "=l"(r) : "f"(lo), "f"(hi)); return r;
}
__device__ __forceinline__ void unpack2(u64 v, float& lo, float& hi) {
    asm("mov.b64 {%0, %1}, %2;" : "=f"(lo), "=f"(hi) : "l"(v));
}
__device__ __forceinline__ u64 ffma2(u64 a, u64 b, u64 c) {
    u64 d; asm("fma.rn.f32x2 %0, %1, %2, %3;" : "=l"(d) : "l"(a), "l"(b), "l"(c));
    return d;
}

// dir=0: owned=pred, other=target (min_p2t). dir=1: swapped.
// Row-only form, measured at the FFMA-pipe floor (536M pairs x 3 FFMA at
// rt=2 -> ~170k cyc). This exact configuration benched 77.6us (R8 champion).
__global__ void __launch_bounds__(THREADS, 5)
chamfer_min_kernel(const float* __restrict__ pred, const float* __restrict__ target) {
    const int dir = blockIdx.z;
    const float* __restrict__ A  = dir ? target : pred;
    const float* __restrict__ Bp = dir ? pred : target;
    unsigned int* __restrict__ outenc = g_enc[dir];

    const int b      = blockIdx.y;
    const int tile   = blockIdx.x / NSPLIT;
    const int jsplit = blockIdx.x % NSPLIT;
    const int tid    = threadIdx.x;

    __shared__ u64 shx[TNP], shy[TNP], shz[TNP], shw[TNP];

    u64 nx2[RM], ny2[RM], nz2[RM];
    float p2[RM], m[RM];
    const int ibase = tile * (THREADS * RM) + tid;
#pragma unroll
    for (int r = 0; r < RM; r++) {
        const int i = ibase + r * THREADS;
        const float* p = A + ((size_t)b * KK + i) * 3;
        float x = p[0], y = p[1], z = p[2];
        nx2[r] = pack2(-x, -x);
        ny2[r] = pack2(-y, -y);
        nz2[r] = pack2(-z, -z);
        p2[r] = x * x + y * y + z * z;
        m[r] = CUDART_INF_F;
    }

    // Load + pack this block's single target tile (threads 0..127).
    const int j0 = jsplit * TN;
    if (tid < TNP) {
        const float* t = Bp + ((size_t)b * KK + j0 + 2 * tid) * 3;
        float x0 = t[0], y0 = t[1], z0 = t[2];
        float x1 = t[3], y1 = t[4], z1 = t[5];
        shx[tid] = pack2(x0, x1);
        shy[tid] = pack2(y0, y1);
        shz[tid] = pack2(z0, z1);
        shw[tid] = pack2(0.5f * (x0 * x0 + y0 * y0 + z0 * z0),
                         0.5f * (x1 * x1 + y1 * y1 + z1 * z1));
    }
    __syncthreads();

    // v_j = 0.5*|t_j|^2 - dot(p, t_j); min over j.  d2 = p2 + 2*min(v).
#pragma unroll 4
    for (int jp = 0; jp < TNP; jp++) {
        const u64 tx = shx[jp], ty = shy[jp], tz = shz[jp], tw = shw[jp];
#pragma unroll
        for (int r = 0; r < RM; r++) {
            u64 v = ffma2(nz2[r], tz, tw);
            v = ffma2(ny2[r], ty, v);
            v = ffma2(nx2[r], tx, v);
            float vlo, vhi;
            unpack2(v, vlo, vhi);
            m[r] = fminf(m[r], vlo);
            m[r] = fminf(m[r], vhi);
        }
    }

#pragma unroll
    for (int r = 0; r < RM; r++) {
        float d2 = fmaf(2.0f, m[r], p2[r]);
        float d  = sqrtf(fmaxf(d2, 0.0f));
        atomicMax(&outenc[(size_t)b * KK + ibase + r * THREADS],
                  ~__float_as_uint(d));
    }
}

// Multi-block reduce + slot reset for graph replay; the LAST block to finish
// (threadfence + counter) also performs the final deterministic combine,
// saving a separate kernel launch. g_part values are identical per replay,
// so the result is replay-deterministic regardless of which block is last.
__global__ void __launch_bounds__(RTHREADS)
reduce_kernel(const float* __restrict__ mask, float* __restrict__ out) {
    float s0 = 0.f, s1 = 0.f, s2 = 0.f;
    for (int i = blockIdx.x * RTHREADS + threadIdx.x; i < BB * KK;
         i += RBLOCKS * RTHREADS) {
        float mk = mask[i];
        float d0 = __uint_as_float(~g_enc[0][i]);
        float d1 = __uint_as_float(~g_enc[1][i]);
        g_enc[0][i] = 0u;
        g_enc[1][i] = 0u;
        s0 = fmaf(d0, mk, s0);
        s1 = fmaf(d1, mk, s1);
        s2 += mk;
    }
    __shared__ float sh[3][RTHREADS];
    const int tid = threadIdx.x;
    sh[0][tid] = s0; sh[1][tid] = s1; sh[2][tid] = s2;
    __syncthreads();
    for (int off = RTHREADS / 2; off > 0; off >>= 1) {
        if (tid < off) {
            sh[0][tid] += sh[0][tid + off];
            sh[1][tid] += sh[1][tid + off];
            sh[2][tid] += sh[2][tid + off];
        }
        __syncthreads();
    }

    __shared__ unsigned int s_last;
    if (tid == 0) {
        g_part[0][blockIdx.x] = sh[0][0];
        g_part[1][blockIdx.x] = sh[1][0];
        g_part[2][blockIdx.x] = sh[2][0];
        __threadfence();                       // publish g_part before counting
        s_last = (atomicAdd(&g_done, 1u) == RBLOCKS - 1u);
    }
    __syncthreads();

    if (s_last) {
        if (tid < 64) {                        // 2 warps do the final combine
            float a = g_part[0][tid], b = g_part[1][tid], c = g_part[2][tid];
#pragma unroll
            for (int off = 16; off > 0; off >>= 1) {
                a += __shfl_down_sync(0xFFFFFFFFu, a, off);
                b += __shfl_down_sync(0xFFFFFFFFu, b, off);
                c += __shfl_down_sync(0xFFFFFFFFu, c, off);
            }
            if ((tid & 31) == 0) {
                sh[0][tid >> 5] = a; sh[1][tid >> 5] = b; sh[2][tid >> 5] = c;
            }
        }
        __syncthreads();
        if (tid == 0) {
            float f0 = sh[0][0] + sh[0][1];
            float f1 = sh[1][0] + sh[1][1];
            float f2 = sh[2][0] + sh[2][1];
            out[0] = (f0 + f1) / (2.0f * (f2 + 1e-8f));
            g_done = 0u;                       // reset for next graph replay
        }
    }
}

extern "C" void kernel_launch(void* const* d_in, const int* in_sizes, int n_in,
                              void* d_out, int out_size) {
    const float* pred   = (const float*)d_in[0];
    const float* target = (const float*)d_in[1];
    const float* mask   = (const float*)d_in[2];
    float* out = (float*)d_out;

    // tiles(8) * NSPLIT(32) = 256;  256 x 4 x 2 = 2048 blocks
    dim3 grid(KK / (THREADS * RM) * NSPLIT, BB, 2);
    chamfer_min_kernel<<<grid, THREADS>>>(pred, target);

    reduce_kernel<<<RBLOCKS, RTHREADS>>>(mask, out);
}